// round 10
// baseline (speedup 1.0000x reference)
#include <cuda_runtime.h>
#include <cstring>

#define VOCAB 512
#define EMBD  128
#define HID   64
#define BATCH 256
#define TLEN  1024
#define WS2_STRIDE 68   // floats; 272B row stride: 16B-aligned, optimal 4-phase LDS.128

// Precomputed layer-0 input table: P0[v][j] = bih0[j] + bhh0[j] + emb[v] . Wih0[j]
__device__ float g_P0[VOCAB * HID];

// ---------------------------------------------------------------------------
// Kernel 1: precompute P0 (512 x 64, each a 128-dot). Trivial cost.
// ---------------------------------------------------------------------------
__global__ void precompute_P0(const float* __restrict__ emb,
                              const float* __restrict__ Wih0,
                              const float* __restrict__ bih0,
                              const float* __restrict__ bhh0)
{
    __shared__ float embs[EMBD];
    __shared__ float ws[HID * (EMBD + 1)];
    const int v = blockIdx.x;
    const int j = threadIdx.x;               // 64 threads

    embs[j]      = emb[v * EMBD + j];
    embs[j + 64] = emb[v * EMBD + j + 64];
    for (int r = 0; r < HID; r++) {
        ws[r * (EMBD + 1) + j]      = Wih0[r * EMBD + j];
        ws[r * (EMBD + 1) + j + 64] = Wih0[r * EMBD + j + 64];
    }
    __syncthreads();

    float acc = bih0[j] + bhh0[j];
    #pragma unroll
    for (int k = 0; k < EMBD; k++)
        acc += embs[k] * ws[j * (EMBD + 1) + k];
    g_P0[v * HID + j] = acc;
}

// ---------------------------------------------------------------------------
// Packed f32x2 helpers (Blackwell FFMA2 / FADD2 — PTX-only)
// ---------------------------------------------------------------------------
__device__ __forceinline__ void ffma2(unsigned long long& d,
                                      unsigned long long a,
                                      unsigned long long b)
{
    asm("fma.rn.f32x2 %0, %1, %2, %0;" : "+l"(d) : "l"(a), "l"(b));
}

__device__ __forceinline__ unsigned long long fadd2(unsigned long long a,
                                                    unsigned long long b)
{
    unsigned long long d;
    asm("add.rn.f32x2 %0, %1, %2;" : "=l"(d) : "l"(a), "l"(b));
    return d;
}

__device__ __forceinline__ float hsum2(unsigned long long a)
{
    float2 f;
    memcpy(&f, &a, 8);
    return f.x + f.y;
}

__device__ __forceinline__ unsigned long long pack2(float lo, float hi)
{
    float2 f; f.x = lo; f.y = hi;
    unsigned long long d;
    memcpy(&d, &f, 8);
    return d;
}

__device__ __forceinline__ float tanh_fast(float x)
{
    float y;
    asm("tanh.approx.f32 %0, %1;" : "=f"(y) : "f"(x));
    return y;
}

// ---------------------------------------------------------------------------
// Kernel 2: fused 2-layer RNN scan + head.
//
// Grid: 128 CTAs x 128 threads; CTA owns 2 batches (group g = tid>>6, 64
// threads = warps {2g,2g+1}, one warp per SMSP, independent named barrier).
// Thread u owns hidden unit u for BOTH layers.
//
// R8: Whh1 weights live in SHARED (row stride 68 floats) instead of 64
// registers -> ~60 registers of scheduling slack so ptxas can hoist the
// LDS streams and hide their latency. Whh0/Wih1 stay register-resident
// (64 f32x2 regs). Sentinel token entry removes the per-phase clamp;
// a/b-pass ordered for operand .reuse (vx,vx,vy,vy).
// ---------------------------------------------------------------------------
__global__ __launch_bounds__(128, 1)
void rnn_scan_kernel(const int*   __restrict__ x,
                     const float* __restrict__ Whh0,
                     const float* __restrict__ Wih1,
                     const float* __restrict__ Whh1,
                     const float* __restrict__ bih1,
                     const float* __restrict__ bhh1,
                     const float* __restrict__ W1,
                     const float* __restrict__ b1,
                     const float* __restrict__ W2,
                     const float* __restrict__ b2,
                     float*       __restrict__ out)
{
    extern __shared__ float smem[];
    // layout (floats): P0s[32768] | xs[2*(TLEN+1)+2 pad] | hbuf[512] | ws2[64*68]
    float* P0s  = smem;
    int*   xs   = (int*)(smem + VOCAB * HID);            // 2*(TLEN+1) = 2050, pad to 2052
    float* hbuf = smem + VOCAB * HID + 2052;             // 16B-aligned
    float* ws2  = hbuf + 512;                            // Whh1, stride 68
    const int XROW = TLEN + 1;

    const int tid  = threadIdx.x;
    const int g    = tid >> 6;       // batch group within CTA
    const int u    = tid & 63;       // hidden unit
    const int bidx = blockIdx.x * 2 + g;

    // ---- stage P0 table (float4)
    {
        const float4* srcp = (const float4*)g_P0;
        float4*       dstp = (float4*)P0s;
        for (int i = tid; i < (VOCAB * HID) / 4; i += 128) dstp[i] = srcp[i];
    }
    // ---- stage token rows with sentinel at index TLEN
    for (int i = tid; i < 2 * XROW; i += 128) {
        int b = i / XROW, t = i % XROW;
        int tt = (t < TLEN) ? t : (TLEN - 1);
        xs[i] = x[(blockIdx.x * 2 + b) * TLEN + tt];
    }
    // ---- zero h buffers
    for (int i = tid; i < 512; i += 128) hbuf[i] = 0.0f;
    // ---- stage Whh1 into shared, row stride 68
    for (int i = tid; i < HID * HID; i += 128)
        ws2[(i >> 6) * WS2_STRIDE + (i & 63)] = Whh1[i];

    // ---- register weights: Whh0 and Wih1 (64 u64 = 128 floats)
    unsigned long long w0p[32], w1p[32];
    {
        const unsigned long long* a  = (const unsigned long long*)(Whh0 + u * HID);
        const unsigned long long* bq = (const unsigned long long*)(Wih1 + u * HID);
        #pragma unroll
        for (int k = 0; k < 32; k++) { w0p[k] = a[k]; w1p[k] = bq[k]; }
    }
    // loop-invariant layer-1 bias, packed for accumulator init
    const unsigned long long c1pack = pack2(bih1[u] + bhh1[u], 0.0f);
    // this thread's Whh1 row in shared
    const ulonglong2* w2row = (const ulonglong2*)(ws2 + u * WS2_STRIDE);

    __syncthreads();

    // per-group buffers (floats, relative to hb): h0 @ {0,64}, h1 @ {128,192}
    float* hb = hbuf + g * 256;
    const int barid = 1 + g;
    const int* xrow = xs + g * XROW;

    // ---- peeled phase 0: h0[0] = tanh(P0[tok0]); h1[-1] stays 0
    hb[64 + u] = tanh_fast(P0s[xrow[0] * HID + u]);
    float p0v = P0s[xrow[1] * HID + u];   // carried prefetch for phase 1
    asm volatile("bar.sync %0, 64;" :: "r"(barid) : "memory");

    int roff = 64;   // phase 1 reads h0[0] at offset 64

    for (int p = 1; p < TLEN; p++) {
        const float* rp = hb + roff;            // h0[p-1] @ rp, h1[p-2] @ rp+128
        float*       wp = hb + (roff ^ 64);     // h0[p] target, h1[p-1] @ +128

        // ---- pass over h0[p-1]: L0 (a*) and L1a (b*) share loads; ordered
        // vx,vx,vy,vy for operand-reuse
        unsigned long long a0 = pack2(p0v, 0.0f), a1 = 0, b0 = 0, b1 = 0;
        {
            const ulonglong2* hv2 = (const ulonglong2*)rp;
            #pragma unroll
            for (int jj = 0; jj < 16; jj++) {
                ulonglong2 v = hv2[jj];
                ffma2(a0, v.x, w0p[2 * jj]);
                ffma2(b0, v.x, w1p[2 * jj]);
                ffma2(a1, v.y, w0p[2 * jj + 1]);
                ffma2(b1, v.y, w1p[2 * jj + 1]);
            }
        }

        // ---- prefetch next phase's P0 (LDS chain hides under c-pass)
        const float p0n = P0s[xrow[p + 1] * HID + u];

        // ---- pass over h1[p-2]: L1b, weights streamed from shared
        unsigned long long c0 = c1pack, c1b = 0;
        {
            const ulonglong2* gv2 = (const ulonglong2*)(rp + 128);
            #pragma unroll
            for (int jj = 0; jj < 16; jj++) {
                ulonglong2 v = gv2[jj];
                ulonglong2 m = w2row[jj];
                ffma2(c0,  v.x, m.x);
                ffma2(c1b, v.y, m.y);
            }
        }

        // ---- finalize h0[p]  (bias already inside a0)
        wp[u] = tanh_fast(hsum2(fadd2(a0, a1)));

        // ---- finalize h1[p-1]  (bias already inside c0)
        wp[128 + u] = tanh_fast(hsum2(fadd2(fadd2(b0, b1), fadd2(c0, c1b))));

        p0v = p0n;
        roff ^= 64;
        asm volatile("bar.sync %0, 64;" :: "r"(barid) : "memory");
    }

    // ---- peeled phase TLEN: h1[T-1] = tanh(Wih1.h0[T-1] + Whh1.h1[T-2] + c1)
    // after the loop roff == 0: h0[T-1] @ hb+0, h1[T-2] @ hb+128; write @ hb+192.
    {
        unsigned long long b0 = 0, b1 = 0, c0 = c1pack, c1b = 0;
        const ulonglong2* hv2 = (const ulonglong2*)hb;
        const ulonglong2* gv2 = (const ulonglong2*)(hb + 128);
        #pragma unroll
        for (int jj = 0; jj < 16; jj++) {
            ulonglong2 v = hv2[jj];
            ffma2(b0, v.x, w1p[2 * jj]);
            ffma2(b1, v.y, w1p[2 * jj + 1]);
            ulonglong2 w = gv2[jj];
            ulonglong2 m = w2row[jj];
            ffma2(c0,  w.x, m.x);
            ffma2(c1b, w.y, m.y);
        }
        hb[192 + u] = tanh_fast(hsum2(fadd2(fadd2(b0, b1), fadd2(c0, c1b))));
    }
    asm volatile("bar.sync %0, 64;" :: "r"(barid) : "memory");

    const float* h1f = hb + 192;   // h1[T-1]

    // ---- head: y = relu(h1f @ W1^T + b1) @ W2^T + b2  (first warp of group)
    if (u < 32) {
        float acc = b1[u];
        #pragma unroll
        for (int k = 0; k < HID; k++)
            acc += W1[u * HID + k] * h1f[k];
        acc = fmaxf(acc, 0.0f);
        float s = acc * W2[u];
        #pragma unroll
        for (int off = 16; off; off >>= 1)
            s += __shfl_down_sync(0xffffffffu, s, off);
        if (u == 0) out[bidx] = s + b2[0];
    }
}

// ---------------------------------------------------------------------------
extern "C" void kernel_launch(void* const* d_in, const int* in_sizes, int n_in,
                              void* d_out, int out_size)
{
    const int*   x    = (const int*)  d_in[0];
    const float* emb  = (const float*)d_in[1];
    const float* Wih0 = (const float*)d_in[2];
    const float* Whh0 = (const float*)d_in[3];
    const float* bih0 = (const float*)d_in[4];
    const float* bhh0 = (const float*)d_in[5];
    const float* Wih1 = (const float*)d_in[6];
    const float* Whh1 = (const float*)d_in[7];
    const float* bih1 = (const float*)d_in[8];
    const float* bhh1 = (const float*)d_in[9];
    const float* W1   = (const float*)d_in[10];
    const float* b1   = (const float*)d_in[11];
    const float* W2   = (const float*)d_in[12];
    const float* b2   = (const float*)d_in[13];
    float* out = (float*)d_out;

    precompute_P0<<<VOCAB, 64>>>(emb, Wih0, bih0, bhh0);

    // floats: P0 32768 + xs 2052 + hbuf 512 + ws2 64*68
    const int smem_bytes = (VOCAB * HID + 2052 + 512 + HID * WS2_STRIDE) * 4;
    cudaFuncSetAttribute(rnn_scan_kernel,
                         cudaFuncAttributeMaxDynamicSharedMemorySize, smem_bytes);
    rnn_scan_kernel<<<BATCH / 2, 128, smem_bytes>>>(
        x, Whh0, Wih1, Whh1, bih1, bhh1, W1, b1, W2, b2, out);
}

// round 12
// speedup vs baseline: 1.1763x; 1.1763x over previous
#include <cuda_runtime.h>
#include <cstring>

#define VOCAB 512
#define EMBD  128
#define HID   64
#define BATCH 256
#define TLEN  1024

// Precomputed layer-0 input table: P0[v][j] = bih0[j] + bhh0[j] + emb[v] . Wih0[j]
__device__ float g_P0[VOCAB * HID];

// ---------------------------------------------------------------------------
// Kernel 1: precompute P0 (512 x 64, each a 128-dot). Trivial cost.
// ---------------------------------------------------------------------------
__global__ void precompute_P0(const float* __restrict__ emb,
                              const float* __restrict__ Wih0,
                              const float* __restrict__ bih0,
                              const float* __restrict__ bhh0)
{
    __shared__ float embs[EMBD];
    __shared__ float ws[HID * (EMBD + 1)];
    const int v = blockIdx.x;
    const int j = threadIdx.x;               // 64 threads

    embs[j]      = emb[v * EMBD + j];
    embs[j + 64] = emb[v * EMBD + j + 64];
    for (int r = 0; r < HID; r++) {
        ws[r * (EMBD + 1) + j]      = Wih0[r * EMBD + j];
        ws[r * (EMBD + 1) + j + 64] = Wih0[r * EMBD + j + 64];
    }
    __syncthreads();

    float acc = bih0[j] + bhh0[j];
    #pragma unroll
    for (int k = 0; k < EMBD; k++)
        acc += embs[k] * ws[j * (EMBD + 1) + k];
    g_P0[v * HID + j] = acc;
}

// ---------------------------------------------------------------------------
// Packed f32x2 helpers (Blackwell FFMA2 / FADD2 — PTX-only)
// ---------------------------------------------------------------------------
__device__ __forceinline__ void ffma2(unsigned long long& d,
                                      unsigned long long a,
                                      unsigned long long b)
{
    asm("fma.rn.f32x2 %0, %1, %2, %0;" : "+l"(d) : "l"(a), "l"(b));
}

__device__ __forceinline__ unsigned long long fadd2(unsigned long long a,
                                                    unsigned long long b)
{
    unsigned long long d;
    asm("add.rn.f32x2 %0, %1, %2;" : "=l"(d) : "l"(a), "l"(b));
    return d;
}

__device__ __forceinline__ float hsum2(unsigned long long a)
{
    float2 f;
    memcpy(&f, &a, 8);
    return f.x + f.y;
}

__device__ __forceinline__ unsigned long long pack2(float lo, float hi)
{
    float2 f; f.x = lo; f.y = hi;
    unsigned long long d;
    memcpy(&d, &f, 8);
    return d;
}

__device__ __forceinline__ float tanh_fast(float x)
{
    float y;
    asm("tanh.approx.f32 %0, %1;" : "=f"(y) : "f"(x));
    return y;
}

// ---------------------------------------------------------------------------
// Kernel 2: fused 2-layer RNN scan + head — light/heavy warp specialization.
//
// 128 CTAs x 256 threads; CTA owns 2 batches. Warp w: g = w&1 (batch group),
// role = w>>2 (0 = light, 1 = heavy), unit u = ((w>>1)&1)*32 + lane.
//   light (warps 0-3): h0[p][u] = tanh(P0[tok_p][u] + Whh0[u].h0[p-1])
//                      32 FFMA2, 16 LDS, 32 weight u64
//   heavy (warps 4-7): h1[p-1][u] = tanh(Wih1[u].h0[p-1] + Whh1[u].h1[p-2] + c1)
//                      64 FFMA2, 32 LDS, 64 weight u64
// SMSP s hosts light warp s and heavy warp s+4 of the SAME group -> two
// warps interleave to hide LDS latency and FFMA chains; groups decoupled
// via named barriers (128 threads each). Light and heavy run separate tight
// loops with matched bar.sync counts (1025 each). XOR-toggled h buffers.
// ---------------------------------------------------------------------------
__global__ __launch_bounds__(256, 1)
void rnn_scan_kernel(const int*   __restrict__ x,
                     const float* __restrict__ Whh0,
                     const float* __restrict__ Wih1,
                     const float* __restrict__ Whh1,
                     const float* __restrict__ bih1,
                     const float* __restrict__ bhh1,
                     const float* __restrict__ W1,
                     const float* __restrict__ b1,
                     const float* __restrict__ W2,
                     const float* __restrict__ b2,
                     float*       __restrict__ out)
{
    extern __shared__ float smem[];
    // layout (floats): P0s[32768] | xs[2*1025 -> pad 2052] | hbuf[512]
    float* P0s  = smem;
    int*   xs   = (int*)(smem + VOCAB * HID);
    float* hbuf = smem + VOCAB * HID + 2052;
    const int XROW = TLEN + 1;

    const int tid  = threadIdx.x;
    const int w    = tid >> 5;
    const int lane = tid & 31;
    const int g    = w & 1;                    // batch group
    const int role = w >> 2;                   // 0 light, 1 heavy
    const int u    = ((w >> 1) & 1) * 32 + lane;

    // ---- stage P0 table (float4)
    {
        const float4* srcp = (const float4*)g_P0;
        float4*       dstp = (float4*)P0s;
        for (int i = tid; i < (VOCAB * HID) / 4; i += 256) dstp[i] = srcp[i];
    }
    // ---- stage token rows with sentinel at index TLEN
    for (int i = tid; i < 2 * XROW; i += 256) {
        int b = i / XROW, t = i % XROW;
        int tt = (t < TLEN) ? t : (TLEN - 1);
        xs[i] = x[(blockIdx.x * 2 + b) * TLEN + tt];
    }
    // ---- zero h buffers
    for (int i = tid; i < 512; i += 256) hbuf[i] = 0.0f;
    __syncthreads();

    // per-group buffers (floats, rel. to hb): h0 @ {0,64}, h1 @ {128,192}
    float* hb = hbuf + g * 256;
    const int barid = 1 + g;
    const int* xrow = xs + g * XROW;

    if (role == 0) {
        // ================= LIGHT: layer-0 recurrence =======================
        unsigned long long w0p[32];
        {
            const unsigned long long* a = (const unsigned long long*)(Whh0 + u * HID);
            #pragma unroll
            for (int k = 0; k < 32; k++) w0p[k] = a[k];
        }

        // peeled phase 0: h0[0] = tanh(P0[tok0])
        hb[64 + u] = tanh_fast(P0s[xrow[0] * HID + u]);
        float p0v = P0s[xrow[1] * HID + u];
        asm volatile("bar.sync %0, 128;" :: "r"(barid) : "memory");

        int roff = 64;
        for (int p = 1; p < TLEN; p++) {
            const ulonglong2* hv2 = (const ulonglong2*)(hb + roff);
            unsigned long long a0 = pack2(p0v, 0.0f), a1 = 0, a2 = 0, a3 = 0;
            #pragma unroll
            for (int jj = 0; jj < 16; jj += 2) {
                ulonglong2 v0 = hv2[jj];
                ffma2(a0, v0.x, w0p[2 * jj]);
                ffma2(a1, v0.y, w0p[2 * jj + 1]);
                ulonglong2 v1 = hv2[jj + 1];
                ffma2(a2, v1.x, w0p[2 * jj + 2]);
                ffma2(a3, v1.y, w0p[2 * jj + 3]);
            }
            const float p0n = P0s[xrow[p + 1] * HID + u];   // prefetch (sentinel-safe)
            hb[(roff ^ 64) + u] =
                tanh_fast(hsum2(fadd2(fadd2(a0, a1), fadd2(a2, a3))));
            p0v = p0n;
            roff ^= 64;
            asm volatile("bar.sync %0, 128;" :: "r"(barid) : "memory");
        }
        // match heavy's final iteration
        asm volatile("bar.sync %0, 128;" :: "r"(barid) : "memory");
    } else {
        // ================= HEAVY: layer-1 recurrence =======================
        unsigned long long w1p[32], w2p[32];
        {
            const unsigned long long* bq = (const unsigned long long*)(Wih1 + u * HID);
            const unsigned long long* c  = (const unsigned long long*)(Whh1 + u * HID);
            #pragma unroll
            for (int k = 0; k < 32; k++) { w1p[k] = bq[k]; w2p[k] = c[k]; }
        }
        const unsigned long long c1pack = pack2(bih1[u] + bhh1[u], 0.0f);

        asm volatile("bar.sync %0, 128;" :: "r"(barid) : "memory");

        int roff = 64;    // h0[p-1] offset (matches light's read offset)
        int ro1  = 128;   // h1[p-2] offset; write at ro1^64
        for (int p = 1; p <= TLEN; p++) {
            const ulonglong2* hv2 = (const ulonglong2*)(hb + roff);
            const ulonglong2* gv2 = (const ulonglong2*)(hb + ro1);

            unsigned long long b0 = 0, b1 = 0, b2 = 0, b3 = 0;
            #pragma unroll
            for (int jj = 0; jj < 16; jj += 2) {
                ulonglong2 v0 = hv2[jj];
                ffma2(b0, v0.x, w1p[2 * jj]);
                ffma2(b1, v0.y, w1p[2 * jj + 1]);
                ulonglong2 v1 = hv2[jj + 1];
                ffma2(b2, v1.x, w1p[2 * jj + 2]);
                ffma2(b3, v1.y, w1p[2 * jj + 3]);
            }
            unsigned long long c0 = c1pack, c1b = 0, c2 = 0, c3 = 0;
            #pragma unroll
            for (int jj = 0; jj < 16; jj += 2) {
                ulonglong2 v0 = gv2[jj];
                ffma2(c0,  v0.x, w2p[2 * jj]);
                ffma2(c1b, v0.y, w2p[2 * jj + 1]);
                ulonglong2 v1 = gv2[jj + 1];
                ffma2(c2,  v1.x, w2p[2 * jj + 2]);
                ffma2(c3,  v1.y, w2p[2 * jj + 3]);
            }
            const unsigned long long sb = fadd2(fadd2(b0, b1), fadd2(b2, b3));
            const unsigned long long sc = fadd2(fadd2(c0, c1b), fadd2(c2, c3));
            hb[(ro1 ^ 64) + u] = tanh_fast(hsum2(fadd2(sb, sc)));

            roff ^= 64;
            ro1  ^= 64;
            asm volatile("bar.sync %0, 128;" :: "r"(barid) : "memory");
        }
    }

    // h1[T-1]: heavy's last iteration (p=1024, ro1=192) wrote at offset 128.
    // ---- head: warps 0 (g=0) and 1 (g=1) — both light, already past all bars
    if (w < 2) {
        const float* h1f = hbuf + w * 256 + 128;
        float acc = b1[lane];
        #pragma unroll
        for (int k = 0; k < HID; k++)
            acc += W1[lane * HID + k] * h1f[k];
        acc = fmaxf(acc, 0.0f);
        float s = acc * W2[lane];
        #pragma unroll
        for (int off = 16; off; off >>= 1)
            s += __shfl_down_sync(0xffffffffu, s, off);
        if (lane == 0) out[blockIdx.x * 2 + w] = s + b2[0];
    }
}

// ---------------------------------------------------------------------------
extern "C" void kernel_launch(void* const* d_in, const int* in_sizes, int n_in,
                              void* d_out, int out_size)
{
    const int*   x    = (const int*)  d_in[0];
    const float* emb  = (const float*)d_in[1];
    const float* Wih0 = (const float*)d_in[2];
    const float* Whh0 = (const float*)d_in[3];
    const float* bih0 = (const float*)d_in[4];
    const float* bhh0 = (const float*)d_in[5];
    const float* Wih1 = (const float*)d_in[6];
    const float* Whh1 = (const float*)d_in[7];
    const float* bih1 = (const float*)d_in[8];
    const float* bhh1 = (const float*)d_in[9];
    const float* W1   = (const float*)d_in[10];
    const float* b1   = (const float*)d_in[11];
    const float* W2   = (const float*)d_in[12];
    const float* b2   = (const float*)d_in[13];
    float* out = (float*)d_out;

    precompute_P0<<<VOCAB, 64>>>(emb, Wih0, bih0, bhh0);

    const int smem_bytes = (VOCAB * HID + 2052 + 512) * 4;   // 141,312 B
    cudaFuncSetAttribute(rnn_scan_kernel,
                         cudaFuncAttributeMaxDynamicSharedMemorySize, smem_bytes);
    rnn_scan_kernel<<<BATCH / 2, 256, smem_bytes>>>(
        x, Whh0, Wih1, Whh1, bih1, bhh1, W1, b1, W2, b2, out);
}